// round 15
// baseline (speedup 1.0000x reference)
#include <cuda_runtime.h>
#include <cuda_bf16.h>
#include <cstdint>
#include <cstddef>

// ---------------------------------------------------------------------------
// Problem constants
//   B=2, DIM=256, H=W=64, HEADS=8 (HC=32), HG=2 (GC=128), STRIDE=2,
//   WS=8 (NW=64 windows of WT=64 queries), RH=RW=32 (R=1024), MLP_HID=1024
// ---------------------------------------------------------------------------

#define NB      2
#define CDIM    256
#define HWPIX   4096            // 64*64
#define HEADS   8
#define HC      32
#define HG      2
#define GC      128
#define RPTS    1024            // R
#define NWIN    64              // NW
#define NPIX_S  65536           // NW * R
#define MLPH    1024

// ----------------------------- scratch ------------------------------------
__device__ float g_xaT [NB * HWPIX * CDIM];            // LN1 out, pixel-major
__device__ float g_q   [NB * CDIM * HWPIX];            // q conv out, C-major
__device__ float g_oT  [4 * 64 * 128];                 // bn+gelu out, pixel-major
__device__ float g_offr[4 * 2048 * 64];                // off4 out, C-major
__device__ __nv_bfloat16 g_pk [4 * HWPIX * CDIM];      // partial k maps, bf16 pixel-major
__device__ __nv_bfloat16 g_pv [4 * HWPIX * CDIM];      // partial v maps, bf16 pixel-major
__device__ float g_attnT[NB * HWPIX * CDIM];           // attention out, pixel-major
__device__ float g_x2  [NB * HWPIX * CDIM];            // x + proj, pixel-major
__device__ float g_xmT [NB * HWPIX * CDIM];            // LN2 out, pixel-major
__device__ float g_hidT[(size_t)NB * HWPIX * MLPH];    // mlp hidden, pixel-major

// ----------------------------- helpers ------------------------------------
__device__ __forceinline__ float geluf(float v) {
    return 0.5f * v * (1.0f + erff(v * 0.70710678118654752f));
}

__device__ __forceinline__ float to_tf32(float x) {
    uint32_t u;
    asm("cvt.rna.tf32.f32 %0, %1;" : "=r"(u) : "f"(x));
    return __uint_as_float(u);
}

__device__ __forceinline__ void mma_tf32(float* d, const uint32_t* a, const uint32_t* b) {
    asm volatile(
        "mma.sync.aligned.m16n8k8.row.col.f32.tf32.tf32.f32 "
        "{%0,%1,%2,%3}, {%4,%5,%6,%7}, {%8,%9}, {%0,%1,%2,%3};"
        : "+f"(d[0]), "+f"(d[1]), "+f"(d[2]), "+f"(d[3])
        : "r"(a[0]), "r"(a[1]), "r"(a[2]), "r"(a[3]), "r"(b[0]), "r"(b[1]));
}

// Fast exp on the FMA pipe. Degree-5 poly for 2^f, rel err ~8e-5.
__device__ __forceinline__ float fexp(float x) {
    float y = x * 1.4426950408889634f;
    y = fmaxf(y, -126.0f);
    float fi = floorf(y);
    float f = y - fi;
    float p = 0.0013333558f;
    p = fmaf(p, f, 0.0096181291f);
    p = fmaf(p, f, 0.0555041087f);
    p = fmaf(p, f, 0.2402264923f);
    p = fmaf(p, f, 0.6931471806f);
    p = fmaf(p, f, 1.0f);
    int e = (int)fi;
    return p * __int_as_float((e + 127) << 23);
}

// unpack 8 bf16 (one uint4) to floats
__device__ __forceinline__ void unp8(const uint4& u, float* f) {
    const __nv_bfloat162* h = (const __nv_bfloat162*)&u;
    #pragma unroll
    for (int i = 0; i < 4; i++) {
        float2 t = __bfloat1622float2(h[i]);
        f[2 * i] = t.x; f[2 * i + 1] = t.y;
    }
}

// --------------------- LayerNorm 1 (C-major in, coalesced) -----------------
__global__ __launch_bounds__(256) void ln1_kernel(
    const float* __restrict__ in, const float* __restrict__ gam,
    const float* __restrict__ bet, float* __restrict__ outT)
{
    __shared__ float S[256][33];
    __shared__ float p1[8][32], p2[8][32];
    __shared__ float muS[32], riS[32];
    const int blk = blockIdx.x;          // 256 blocks
    const int b   = blk >> 7;
    const int hw0 = (blk & 127) * 32;
    const int t   = threadIdx.x;
    const int lane = t & 31, wrp = t >> 5;

    const float* ip = in + (size_t)b * CDIM * HWPIX + hw0 + lane;
    #pragma unroll
    for (int it = 0; it < 32; it++) {
        int c = wrp + it * 8;
        S[c][lane] = ip[(size_t)c * HWPIX];
    }
    __syncthreads();

    {
        int cb = wrp * 32;
        float s1 = 0.f, s2 = 0.f;
        #pragma unroll
        for (int i = 0; i < 32; i++) {
            float v = S[cb + i][lane];
            s1 += v;
            s2 = fmaf(v, v, s2);
        }
        p1[wrp][lane] = s1;
        p2[wrp][lane] = s2;
    }
    __syncthreads();
    if (t < 32) {
        float s1 = 0.f, s2 = 0.f;
        #pragma unroll
        for (int i = 0; i < 8; i++) { s1 += p1[i][t]; s2 += p2[i][t]; }
        float mu = s1 * (1.0f / 256.0f);
        float var = s2 * (1.0f / 256.0f) - mu * mu;
        muS[t] = mu;
        riS[t] = rsqrtf(var + 1e-5f);
    }
    __syncthreads();

    #pragma unroll
    for (int it = 0; it < 32; it++) {
        int p = wrp * 4 + (it & 3);
        int c = lane + (it >> 2) * 32;
        float v = (S[c][p] - muS[p]) * riS[p] * gam[c] + bet[c];
        outT[((size_t)b * HWPIX + hw0 + p) * 256 + c] = v;
    }
}

// ----------------------------- LayerNorm (generic strides) -----------------
__global__ __launch_bounds__(256) void ln_kernel(
    const float* __restrict__ in, const float* __restrict__ gam,
    const float* __restrict__ bet, float* __restrict__ outT,
    size_t bStride, size_t cStride, size_t pStride)
{
    int p  = blockIdx.x;            // 0..8191
    int b  = p >> 12;
    int hw = p & 4095;
    const float* ip = in + (size_t)b * bStride + (size_t)hw * pStride;
    int c = threadIdx.x;
    float v = ip[(size_t)c * cStride];
    float s1 = v, s2 = v * v;
    #pragma unroll
    for (int d = 16; d > 0; d >>= 1) {
        s1 += __shfl_xor_sync(0xffffffffu, s1, d);
        s2 += __shfl_xor_sync(0xffffffffu, s2, d);
    }
    __shared__ float sm1[8], sm2[8];
    __shared__ float mu_s, ri_s;
    int wid = c >> 5;
    if ((c & 31) == 0) { sm1[wid] = s1; sm2[wid] = s2; }
    __syncthreads();
    if (c == 0) {
        float t1 = 0.f, t2 = 0.f;
        #pragma unroll
        for (int i = 0; i < 8; i++) { t1 += sm1[i]; t2 += sm2[i]; }
        float mu  = t1 * (1.0f / 256.0f);
        float var = t2 * (1.0f / 256.0f) - mu * mu;
        mu_s = mu;
        ri_s = rsqrtf(var + 1e-5f);
    }
    __syncthreads();
    outT[(size_t)p * 256 + c] = (v - mu_s) * ri_s * gam[c] + bet[c];
}

// ----------------------------- GEMM (TN, TF32 tensor core) ------------------
#define GF_OUT_NMAJOR 1
#define GF_RES_NMAJOR 2
#define GF_GELU       4
#define GF_GROUPED    8
#define GF_OUT_BF16   16

__global__ __launch_bounds__(256) void gemm_tn(
    const float* __restrict__ A, int lda,
    const float* __restrict__ Bm, int ldb, size_t bZ,
    const float* __restrict__ bias, const float* __restrict__ res,
    float* __restrict__ C, int M, int N, int K, int flags)
{
    __shared__ float As[128][36];
    __shared__ float Bs[64][36];
    const int b  = blockIdx.z;
    const int m0 = blockIdx.y * 128;
    const int n0 = blockIdx.x * 64;
    const float* Ab = A;
    const float* Bb;
    if (flags & GF_GROUPED) {
        Ab = A + (b & 1) * 128;
        Bb = Bm + (size_t)(b >> 1) * ((size_t)HWPIX * 256) + (b & 1) * 128;
    } else {
        Bb = Bm + (size_t)b * bZ;
    }
    const int tid  = threadIdx.x;
    const int warp = tid >> 5, lane = tid & 31;
    const int g = lane >> 2, tg = lane & 3;
    const int wm = warp & 3;
    const int wn = warp >> 2;

    float acc[2][4][4];
    #pragma unroll
    for (int mi = 0; mi < 2; mi++)
        #pragma unroll
        for (int nj = 0; nj < 4; nj++)
            #pragma unroll
            for (int e = 0; e < 4; e++) acc[mi][nj][e] = 0.f;

    for (int k0 = 0; k0 < K; k0 += 32) {
        #pragma unroll
        for (int i = 0; i < 4; i++) {
            int e = tid + i * 256;
            int row = e >> 3, c4 = (e & 7) << 2;
            float4 a = *(const float4*)(Ab + (size_t)(m0 + row) * lda + k0 + c4);
            As[row][c4    ] = to_tf32(a.x);
            As[row][c4 + 1] = to_tf32(a.y);
            As[row][c4 + 2] = to_tf32(a.z);
            As[row][c4 + 3] = to_tf32(a.w);
        }
        #pragma unroll
        for (int i = 0; i < 2; i++) {
            int e = tid + i * 256;
            int row = e >> 3, c4 = (e & 7) << 2;
            float4 v = *(const float4*)(Bb + (size_t)(n0 + row) * ldb + k0 + c4);
            Bs[row][c4    ] = to_tf32(v.x);
            Bs[row][c4 + 1] = to_tf32(v.y);
            Bs[row][c4 + 2] = to_tf32(v.z);
            Bs[row][c4 + 3] = to_tf32(v.w);
        }
        __syncthreads();

        #pragma unroll
        for (int kk = 0; kk < 4; kk++) {
            int kb = kk * 8;
            uint32_t af[2][4], bf[4][2];
            #pragma unroll
            for (int mi = 0; mi < 2; mi++) {
                int mr = wm * 32 + mi * 16;
                af[mi][0] = __float_as_uint(As[mr + g    ][kb + tg    ]);
                af[mi][1] = __float_as_uint(As[mr + g + 8][kb + tg    ]);
                af[mi][2] = __float_as_uint(As[mr + g    ][kb + tg + 4]);
                af[mi][3] = __float_as_uint(As[mr + g + 8][kb + tg + 4]);
            }
            #pragma unroll
            for (int nj = 0; nj < 4; nj++) {
                int nr = wn * 32 + nj * 8;
                bf[nj][0] = __float_as_uint(Bs[nr + g][kb + tg    ]);
                bf[nj][1] = __float_as_uint(Bs[nr + g][kb + tg + 4]);
            }
            #pragma unroll
            for (int mi = 0; mi < 2; mi++)
                #pragma unroll
                for (int nj = 0; nj < 4; nj++)
                    mma_tf32(acc[mi][nj], af[mi], bf[nj]);
        }
        __syncthreads();
    }

    #pragma unroll
    for (int mi = 0; mi < 2; mi++) {
        #pragma unroll
        for (int nj = 0; nj < 4; nj++) {
            int nc = n0 + wn * 32 + nj * 8 + tg * 2;
            #pragma unroll
            for (int e = 0; e < 4; e++) {
                int m = m0 + wm * 32 + mi * 16 + g + (e >> 1) * 8;
                int n = nc + (e & 1);
                float v = acc[mi][nj][e];
                if (bias) v += bias[m];
                if (flags & GF_GELU) v = geluf(v);
                if (res) {
                    size_t ri = (flags & GF_RES_NMAJOR)
                        ? ((size_t)b * N + n) * (size_t)M + m
                        : ((size_t)b * M + m) * (size_t)N + n;
                    v += res[ri];
                }
                size_t oi = (flags & GF_OUT_NMAJOR)
                    ? ((size_t)b * N + n) * (size_t)M + m
                    : ((size_t)b * M + m) * (size_t)N + n;
                if (flags & GF_OUT_BF16)
                    ((__nv_bfloat16*)C)[oi] = __float2bfloat16(v);
                else
                    C[oi] = v;
            }
        }
    }
}

// ---------------- fused offset path: 3x dw conv + BN + GELU + transpose -----
// Each channel (g,c) is independent through all three stride-2 depthwise
// convs. One block per channel: 64x64 -> 32x32 -> 16x16 -> 8x8 in smem,
// then BN+GELU and transposed store to oT. Replaces 4 kernels.
__global__ __launch_bounds__(256) void dw_fused(
    const float* __restrict__ qin, const float* __restrict__ w1g,
    const float* __restrict__ w2g, const float* __restrict__ w3g,
    const float* __restrict__ bng, const float* __restrict__ bnb,
    const float* __restrict__ bnm, const float* __restrict__ bnv,
    float* __restrict__ oT)
{
    __shared__ float S1[64][65];
    __shared__ float S2[32][33];
    __shared__ float S3[16][17];
    const int blk = blockIdx.x;       // 512
    const int gI = blk >> 7, c = blk & 127;
    const int tid = threadIdx.x;
    const float* ip = qin + (size_t)(gI * 128 + c) * 4096;

    for (int e = tid; e < 4096; e += 256)
        S1[e >> 6][e & 63] = ip[e];

    float w1[9], w2[9], w3[9];
    #pragma unroll
    for (int i = 0; i < 9; i++) {
        w1[i] = w1g[c * 9 + i];
        w2[i] = w2g[c * 9 + i];
        w3[i] = w3g[c * 9 + i];
    }
    __syncthreads();

    // conv1: 64 -> 32 (4 outputs per thread)
    #pragma unroll
    for (int i = 0; i < 4; i++) {
        int o = tid * 4 + i;
        int oy = o >> 5, ox = o & 31;
        float s = 0.f;
        #pragma unroll
        for (int ky = 0; ky < 3; ky++) {
            int iy = oy * 2 - 1 + ky;
            if (iy < 0 || iy >= 64) continue;
            #pragma unroll
            for (int kx = 0; kx < 3; kx++) {
                int ix = ox * 2 - 1 + kx;
                if (ix < 0 || ix >= 64) continue;
                s = fmaf(S1[iy][ix], w1[ky * 3 + kx], s);
            }
        }
        S2[oy][ox] = s;
    }
    __syncthreads();

    // conv2: 32 -> 16 (1 output per thread)
    {
        int oy = tid >> 4, ox = tid & 15;
        float s = 0.f;
        #pragma unroll
        for (int ky = 0; ky < 3; ky++) {
            int iy = oy * 2 - 1 + ky;
            if (iy < 0 || iy >= 32) continue;
            #pragma unroll
            for (int kx = 0; kx < 3; kx++) {
                int ix = ox * 2 - 1 + kx;
                if (ix < 0 || ix >= 32) continue;
                s = fmaf(S2[iy][ix], w2[ky * 3 + kx], s);
            }
        }
        S3[oy][ox] = s;
    }
    __syncthreads();

    // conv3: 16 -> 8, then BN + GELU + transposed store
    if (tid < 64) {
        int oy = tid >> 3, ox = tid & 7;
        float s = 0.f;
        #pragma unroll
        for (int ky = 0; ky < 3; ky++) {
            int iy = oy * 2 - 1 + ky;
            if (iy < 0 || iy >= 16) continue;
            #pragma unroll
            for (int kx = 0; kx < 3; kx++) {
                int ix = ox * 2 - 1 + kx;
                if (ix < 0 || ix >= 16) continue;
                s = fmaf(S3[iy][ix], w3[ky * 3 + kx], s);
            }
        }
        s = (s - bnm[c]) * rsqrtf(bnv[c] + 1e-5f) * bng[c] + bnb[c];
        s = geluf(s);
        oT[(size_t)(gI * 64 + oy * 8 + ox) * 128 + c] = s;
    }
}

// ------- attention with fused sampling, 2 HEADS PER BLOCK -------------------
// Block = (w, h2, b) with h2 = head pair; 256 threads = 8 warps.
// Warps 0-3 -> head 2*h2, warps 4-7 -> head 2*h2+1; each warp owns 16 q rows.
// Gathers fetch the full 128B two-head line per corner -> L2 line traffic
// halved vs per-head blocks, and geometry/Q-staging shared across 2 heads.
__global__ __launch_bounds__(256) void attn_kernel(
    const float* __restrict__ qb, const float* __restrict__ offr,
    const __nv_bfloat16* __restrict__ pkT, const __nv_bfloat16* __restrict__ pvT,
    const float* __restrict__ kb, const float* __restrict__ vb,
    const float* __restrict__ pos, float* __restrict__ outT)
{
    __shared__ float Qs[64][68];       // q rows x 64ch (2 heads, tf32)
    __shared__ float Ks[64][68];       // r rows x 64ch
    __shared__ float VsT[64][73];      // 64ch x 64r
    __shared__ float Ps[2][64][68];    // per-head probs
    __shared__ float4 s_gw[64][2];
    __shared__ int    s_gp[64][2][4];
    __shared__ float  s_kb[64], s_vb[64];

    const int w = blockIdx.x, h2 = blockIdx.y, b = blockIdx.z;
    const int wh = w >> 3, wwx = w & 7;
    const int tid = threadIdx.x;
    const int warp = tid >> 5, lane = tid & 31;
    const int hh = warp >> 2, hwarp = warp & 3;
    const int h = h2 * 2 + hh;
    const int g = lane >> 2, tg = lane & 3;

    if (tid < 64)        s_kb[tid] = kb[h2 * 64 + tid];
    else if (tid < 128)  s_vb[tid - 64] = vb[h2 * 64 + tid - 64];

    // stage Q: both heads' 64 channels (scaled, tf32)
    for (int e = tid; e < 4096; e += 256) {
        int qq = e >> 6, c = e & 63;
        int yy = (wh << 3) + (qq >> 3), xx = (wwx << 3) + (qq & 7);
        Qs[qq][c] = to_tf32(qb[(size_t)(b * 256 + h2 * 64 + c) * HWPIX + yy * 64 + xx] * 0.0625f);
    }

    const int qA = hwarp * 16 + g, qB = qA + 8;
    const int yA = (wh << 3) + (qA >> 3), xA = (wwx << 3) + (qA & 7);
    const int yB = (wh << 3) + (qB >> 3), xB = (wwx << 3) + (qB & 7);
    const float* poshA = pos + h * 127 * 127 + (63 - yA) * 127 + (63 - xA);
    const float* poshB = pos + h * 127 * 127 + (63 - yB) * 127 + (63 - xB);

    float mA = -1e30f, sA = 0.f, mB = -1e30f, sB = 0.f;
    float O[4][4];
    #pragma unroll
    for (int nj = 0; nj < 4; nj++)
        #pragma unroll
        for (int e = 0; e < 4; e++) O[nj][e] = 0.f;

    const int srow = tid >> 2, cq = tid & 3;   // staging: row, 16-ch chunk
    const int chof = h2 * 64 + cq * 16;        // global channel base

    for (int r0 = 0; r0 < 1024; r0 += 64) {
        __syncthreads();
        // (1) geometry (threads 0..127: r = r0 + t/2, group = t&1)
        if (tid < 128) {
            int rr = r0 + (tid >> 1);
            int hg = tid & 1;
            int gg = b * 2 + hg;
            float offRow = offr[(size_t)(gg * 2048 + rr) * 64 + w];
            float offCol = offr[(size_t)(gg * 2048 + 1024 + rr) * 64 + w];
            float rows = fmaf(tanhf(offRow), 0.984375f, (float)((rr >> 5) << 1));
            float cols = fmaf(tanhf(offCol), 0.984375f, (float)((rr & 31) << 1));
            float r0f = floorf(rows), c0f = floorf(cols);
            float fr = rows - r0f, fc = cols - c0f;
            int ri = (int)r0f, ci = (int)c0f;
            bool rv0 = (ri >= 0) && (ri < 64);
            bool rv1 = (ri + 1 >= 0) && (ri + 1 < 64);
            bool cv0 = (ci >= 0) && (ci < 64);
            bool cv1 = (ci + 1 >= 0) && (ci + 1 < 64);
            s_gp[tid >> 1][hg][0] = (rv0 && cv0) ? ri * 64 + ci : -1;
            s_gp[tid >> 1][hg][1] = (rv0 && cv1) ? ri * 64 + ci + 1 : -1;
            s_gp[tid >> 1][hg][2] = (rv1 && cv0) ? (ri + 1) * 64 + ci : -1;
            s_gp[tid >> 1][hg][3] = (rv1 && cv1) ? (ri + 1) * 64 + ci + 1 : -1;
            s_gw[tid >> 1][hg] = make_float4((1.f - fr) * (1.f - fc), (1.f - fr) * fc,
                                             fr * (1.f - fc),         fr * fc);
        }
        __syncthreads();

        // (2) sample-stage K [r][c64] and V transposed [c64][r]
        {
            float ak[16], av[16];
            #pragma unroll
            for (int j = 0; j < 16; j++) {
                ak[j] = s_kb[cq * 16 + j];
                av[j] = s_vb[cq * 16 + j];
            }
            #pragma unroll
            for (int hg = 0; hg < 2; hg++) {
                const float4 ww = s_gw[srow][hg];
                const float wts[4] = {ww.x, ww.y, ww.z, ww.w};
                const __nv_bfloat16* pk0 =
                    pkT + (size_t)(b * 2 + hg) * HWPIX * 256 + chof;
                const __nv_bfloat16* pv0 =
                    pvT + (size_t)(b * 2 + hg) * HWPIX * 256 + chof;
                #pragma unroll
                for (int cn = 0; cn < 4; cn++) {
                    int pix = s_gp[srow][hg][cn];
                    if (pix >= 0) {
                        size_t off = (size_t)pix * 256;
                        uint4 ku0 = *(const uint4*)(pk0 + off);
                        uint4 ku1 = *(const uint4*)(pk0 + off + 8);
                        uint4 vu0 = *(const uint4*)(pv0 + off);
                        uint4 vu1 = *(const uint4*)(pv0 + off + 8);
                        float kf[16], vf[16];
                        unp8(ku0, kf); unp8(ku1, kf + 8);
                        unp8(vu0, vf); unp8(vu1, vf + 8);
                        float wt = wts[cn];
                        #pragma unroll
                        for (int j = 0; j < 16; j++) {
                            ak[j] = fmaf(kf[j], wt, ak[j]);
                            av[j] = fmaf(vf[j], wt, av[j]);
                        }
                    }
                }
            }
            #pragma unroll
            for (int j = 0; j < 16; j++) {
                Ks[srow][cq * 16 + j] = to_tf32(ak[j]);
                VsT[cq * 16 + j][srow] = to_tf32(av[j]);
            }
        }
        __syncthreads();

        // (3a) S = Q Kt (per warp: its head's 32-ch slice)
        float S[8][4];
        #pragma unroll
        for (int nj = 0; nj < 8; nj++)
            #pragma unroll
            for (int e = 0; e < 4; e++) S[nj][e] = 0.f;
        #pragma unroll
        for (int kk = 0; kk < 4; kk++) {
            int kbx = hh * 32 + kk * 8;
            uint32_t af[4];
            af[0] = __float_as_uint(Qs[hwarp * 16 + g    ][kbx + tg    ]);
            af[1] = __float_as_uint(Qs[hwarp * 16 + g + 8][kbx + tg    ]);
            af[2] = __float_as_uint(Qs[hwarp * 16 + g    ][kbx + tg + 4]);
            af[3] = __float_as_uint(Qs[hwarp * 16 + g + 8][kbx + tg + 4]);
            #pragma unroll
            for (int nj = 0; nj < 8; nj++) {
                uint32_t bf[2];
                bf[0] = __float_as_uint(Ks[nj * 8 + g][kbx + tg    ]);
                bf[1] = __float_as_uint(Ks[nj * 8 + g][kbx + tg + 4]);
                mma_tf32(S[nj], af, bf);
            }
        }

        // (3b) relative-position bias
        #pragma unroll
        for (int nj = 0; nj < 8; nj++) {
            int r0c = r0 + nj * 8 + 2 * tg;
            int r1c = r0c + 1;
            int o0 = ((r0c >> 5) << 1) * 127 + ((r0c & 31) << 1);
            int o1 = ((r1c >> 5) << 1) * 127 + ((r1c & 31) << 1);
            S[nj][0] += poshA[o0];
            S[nj][1] += poshA[o1];
            S[nj][2] += poshB[o0];
            S[nj][3] += poshB[o1];
        }

        // (3c) online softmax
        float mxA = -1e30f, mxB = -1e30f;
        #pragma unroll
        for (int nj = 0; nj < 8; nj++) {
            mxA = fmaxf(mxA, fmaxf(S[nj][0], S[nj][1]));
            mxB = fmaxf(mxB, fmaxf(S[nj][2], S[nj][3]));
        }
        mxA = fmaxf(mxA, __shfl_xor_sync(0xffffffffu, mxA, 1));
        mxA = fmaxf(mxA, __shfl_xor_sync(0xffffffffu, mxA, 2));
        mxB = fmaxf(mxB, __shfl_xor_sync(0xffffffffu, mxB, 1));
        mxB = fmaxf(mxB, __shfl_xor_sync(0xffffffffu, mxB, 2));
        float mnA = fmaxf(mA, mxA), mnB = fmaxf(mB, mxB);
        float corrA = fexp(mA - mnA), corrB = fexp(mB - mnB);
        mA = mnA; mB = mnB;

        float suA = 0.f, suB = 0.f;
        #pragma unroll
        for (int nj = 0; nj < 8; nj++) {
            float p0 = fexp(S[nj][0] - mnA);
            float p1 = fexp(S[nj][1] - mnA);
            float p2 = fexp(S[nj][2] - mnB);
            float p3 = fexp(S[nj][3] - mnB);
            suA += p0 + p1;
            suB += p2 + p3;
            int c0 = nj * 8 + 2 * tg;
            Ps[hh][hwarp * 16 + g    ][c0    ] = to_tf32(p0);
            Ps[hh][hwarp * 16 + g    ][c0 + 1] = to_tf32(p1);
            Ps[hh][hwarp * 16 + g + 8][c0    ] = to_tf32(p2);
            Ps[hh][hwarp * 16 + g + 8][c0 + 1] = to_tf32(p3);
        }
        suA += __shfl_xor_sync(0xffffffffu, suA, 1);
        suA += __shfl_xor_sync(0xffffffffu, suA, 2);
        suB += __shfl_xor_sync(0xffffffffu, suB, 1);
        suB += __shfl_xor_sync(0xffffffffu, suB, 2);
        sA = sA * corrA + suA;
        sB = sB * corrB + suB;

        #pragma unroll
        for (int nj = 0; nj < 4; nj++) {
            O[nj][0] *= corrA; O[nj][1] *= corrA;
            O[nj][2] *= corrB; O[nj][3] *= corrB;
        }
        __syncwarp();

        // (3d) O += P Vt (Ps warp-local; VsT stable until loop-top sync)
        #pragma unroll
        for (int kk = 0; kk < 8; kk++) {
            int kbx = kk * 8;
            uint32_t af[4];
            af[0] = __float_as_uint(Ps[hh][hwarp * 16 + g    ][kbx + tg    ]);
            af[1] = __float_as_uint(Ps[hh][hwarp * 16 + g + 8][kbx + tg    ]);
            af[2] = __float_as_uint(Ps[hh][hwarp * 16 + g    ][kbx + tg + 4]);
            af[3] = __float_as_uint(Ps[hh][hwarp * 16 + g + 8][kbx + tg + 4]);
            #pragma unroll
            for (int nj = 0; nj < 4; nj++) {
                uint32_t bf[2];
                bf[0] = __float_as_uint(VsT[hh * 32 + nj * 8 + g][kbx + tg    ]);
                bf[1] = __float_as_uint(VsT[hh * 32 + nj * 8 + g][kbx + tg + 4]);
                mma_tf32(O[nj], af, bf);
            }
        }
    }

    // epilogue: normalize and write (pixel-major, head slice)
    float invA = 1.0f / sA, invB = 1.0f / sB;
    float* opA = outT + ((size_t)b * HWPIX + yA * 64 + xA) * 256 + h * 32;
    float* opB = outT + ((size_t)b * HWPIX + yB * 64 + xB) * 256 + h * 32;
    #pragma unroll
    for (int nj = 0; nj < 4; nj++) {
        int c = nj * 8 + 2 * tg;
        opA[c]     = O[nj][0] * invA;
        opA[c + 1] = O[nj][1] * invA;
        opB[c]     = O[nj][2] * invB;
        opB[c + 1] = O[nj][3] * invB;
    }
}

// ------------------------------ launch -------------------------------------
extern "C" void kernel_launch(void* const* d_in, const int* in_sizes, int n_in,
                              void* d_out, int out_size)
{
    const float* x      = (const float*)d_in[0];
    const float* ln1_g  = (const float*)d_in[1];
    const float* ln1_b  = (const float*)d_in[2];
    const float* q_w    = (const float*)d_in[3];
    const float* q_b    = (const float*)d_in[4];
    const float* k_w    = (const float*)d_in[5];
    const float* k_b    = (const float*)d_in[6];
    const float* v_w    = (const float*)d_in[7];
    const float* v_b    = (const float*)d_in[8];
    const float* off1_w = (const float*)d_in[9];
    const float* off2_w = (const float*)d_in[10];
    const float* off3_w = (const float*)d_in[11];
    const float* bn_g   = (const float*)d_in[12];
    const float* bn_b   = (const float*)d_in[13];
    const float* bn_m   = (const float*)d_in[14];
    const float* bn_v   = (const float*)d_in[15];
    const float* off4_w = (const float*)d_in[16];
    const float* pos    = (const float*)d_in[17];
    const float* proj_w = (const float*)d_in[18];
    const float* proj_b = (const float*)d_in[19];
    const float* ln2_g  = (const float*)d_in[20];
    const float* ln2_b  = (const float*)d_in[21];
    const float* mlp_w1 = (const float*)d_in[22];
    const float* mlp_b1 = (const float*)d_in[23];
    const float* mlp_w2 = (const float*)d_in[24];
    const float* mlp_b2 = (const float*)d_in[25];
    float* out = (float*)d_out;

    float *xaT, *q, *oT, *offr, *attnT, *x2, *xmT, *hidT;
    __nv_bfloat16 *pkB, *pvB;
    cudaGetSymbolAddress((void**)&xaT,   g_xaT);
    cudaGetSymbolAddress((void**)&q,     g_q);
    cudaGetSymbolAddress((void**)&oT,    g_oT);
    cudaGetSymbolAddress((void**)&offr,  g_offr);
    cudaGetSymbolAddress((void**)&pkB,   g_pk);
    cudaGetSymbolAddress((void**)&pvB,   g_pv);
    cudaGetSymbolAddress((void**)&attnT, g_attnT);
    cudaGetSymbolAddress((void**)&x2,    g_x2);
    cudaGetSymbolAddress((void**)&xmT,   g_xmT);
    cudaGetSymbolAddress((void**)&hidT,  g_hidT);

    // 1. LN1 (coalesced transpose kernel): x C-major -> xaT pixel-major
    ln1_kernel<<<256, 256>>>(x, ln1_g, ln1_b, xaT);

    // 2. q = q_w @ xa + q_b  -> C-major (B,256,4096)
    gemm_tn<<<dim3(HWPIX / 64, CDIM / 128, NB), 256>>>(
        q_w, CDIM, xaT, CDIM, (size_t)HWPIX * CDIM,
        q_b, nullptr, q, CDIM, HWPIX, CDIM, 0);

    // 3. fused offset path: 3x dw conv + BN + GELU + transpose -> oT
    dw_fused<<<512, 256>>>(q, off1_w, off2_w, off3_w,
                           bn_g, bn_b, bn_m, bn_v, oT);

    // 4. off4 -> offr C-major (4,2048,64)
    gemm_tn<<<dim3(1, 2048 / 128, 4), 256>>>(
        off4_w, 128, oT, 128, (size_t)64 * 128,
        nullptr, nullptr, offr, 2048, 64, 128, 0);

    // 5a/5b. partial conv maps -> bf16 pixel-major (L2-resident, 8MB total)
    gemm_tn<<<dim3(HWPIX / 64, 2, 4), 256>>>(
        k_w, CDIM, xaT, CDIM, 0,
        nullptr, nullptr, (float*)pkB, CDIM, HWPIX, GC,
        GF_GROUPED | GF_OUT_NMAJOR | GF_OUT_BF16);
    gemm_tn<<<dim3(HWPIX / 64, 2, 4), 256>>>(
        v_w, CDIM, xaT, CDIM, 0,
        nullptr, nullptr, (float*)pvB, CDIM, HWPIX, GC,
        GF_GROUPED | GF_OUT_NMAJOR | GF_OUT_BF16);

    // 6. attention with fused sampling, 2 heads/block -> attnT pixel-major
    attn_kernel<<<dim3(NWIN, HEADS / 2, NB), 256>>>(
        q, offr, pkB, pvB, k_b, v_b, pos, attnT);

    // 7. proj + residual(x, C-major) -> x2 pixel-major
    gemm_tn<<<dim3(HWPIX / 64, CDIM / 128, NB), 256>>>(
        proj_w, CDIM, attnT, CDIM, (size_t)HWPIX * CDIM,
        proj_b, x, x2, CDIM, HWPIX, CDIM, GF_OUT_NMAJOR);

    // 8. LN2 on x2 (pixel-major) -> xmT pixel-major
    ln_kernel<<<8192, 256>>>(x2, ln2_g, ln2_b, xmT,
                             (size_t)HWPIX * CDIM, (size_t)1, (size_t)CDIM);

    // 9. mlp1 + gelu -> hidT pixel-major (B,4096,1024)
    gemm_tn<<<dim3(HWPIX / 64, MLPH / 128, NB), 256>>>(
        mlp_w1, CDIM, xmT, CDIM, (size_t)HWPIX * CDIM,
        mlp_b1, nullptr, hidT, MLPH, HWPIX, CDIM, GF_OUT_NMAJOR | GF_GELU);

    // 10. mlp2 + residual(x2, pixel-major) -> out C-major (B,256,64,64)
    gemm_tn<<<dim3(HWPIX / 64, CDIM / 128, NB), 256>>>(
        mlp_w2, MLPH, hidT, MLPH, (size_t)HWPIX * MLPH,
        mlp_b2, x2, out, CDIM, HWPIX, MLPH, GF_RES_NMAJOR);
}

// round 16
// speedup vs baseline: 1.0685x; 1.0685x over previous
#include <cuda_runtime.h>
#include <cuda_bf16.h>
#include <cstdint>
#include <cstddef>

// ---------------------------------------------------------------------------
// Problem constants
//   B=2, DIM=256, H=W=64, HEADS=8 (HC=32), HG=2 (GC=128), STRIDE=2,
//   WS=8 (NW=64 windows of WT=64 queries), RH=RW=32 (R=1024), MLP_HID=1024
// ---------------------------------------------------------------------------

#define NB      2
#define CDIM    256
#define HWPIX   4096            // 64*64
#define HEADS   8
#define HC      32
#define HG      2
#define GC      128
#define RPTS    1024            // R
#define NWIN    64              // NW
#define NPIX_S  65536           // NW * R
#define MLPH    1024

// ----------------------------- scratch ------------------------------------
__device__ float g_xaT [NB * HWPIX * CDIM];            // LN1 out, pixel-major
__device__ float g_q   [NB * CDIM * HWPIX];            // q conv out, C-major
__device__ float g_oT  [4 * 64 * 128];                 // bn+gelu out, pixel-major
__device__ float g_offr[4 * 2048 * 64];                // off4 out, C-major
__device__ __nv_bfloat16 g_pk [4 * HWPIX * CDIM];      // partial k maps, bf16 pixel-major
__device__ __nv_bfloat16 g_pv [4 * HWPIX * CDIM];      // partial v maps, bf16 pixel-major
__device__ float g_attnT[NB * HWPIX * CDIM];           // attention out, pixel-major
__device__ float g_x2  [NB * HWPIX * CDIM];            // x + proj, pixel-major
__device__ float g_xmT [NB * HWPIX * CDIM];            // LN2 out, pixel-major
__device__ float g_hidT[(size_t)NB * HWPIX * MLPH];    // mlp hidden, pixel-major

// ----------------------------- helpers ------------------------------------
__device__ __forceinline__ float geluf(float v) {
    return 0.5f * v * (1.0f + erff(v * 0.70710678118654752f));
}

__device__ __forceinline__ float to_tf32(float x) {
    uint32_t u;
    asm("cvt.rna.tf32.f32 %0, %1;" : "=r"(u) : "f"(x));
    return __uint_as_float(u);
}

__device__ __forceinline__ void mma_tf32(float* d, const uint32_t* a, const uint32_t* b) {
    asm volatile(
        "mma.sync.aligned.m16n8k8.row.col.f32.tf32.tf32.f32 "
        "{%0,%1,%2,%3}, {%4,%5,%6,%7}, {%8,%9}, {%0,%1,%2,%3};"
        : "+f"(d[0]), "+f"(d[1]), "+f"(d[2]), "+f"(d[3])
        : "r"(a[0]), "r"(a[1]), "r"(a[2]), "r"(a[3]), "r"(b[0]), "r"(b[1]));
}

__device__ __forceinline__ uint32_t smem_u32(const void* p) {
    uint32_t a;
    asm("{ .reg .u64 t; cvta.to.shared.u64 t, %1; cvt.u32.u64 %0, t; }"
        : "=r"(a) : "l"(p));
    return a;
}
__device__ __forceinline__ void cpa16(uint32_t dst, const void* src) {
    asm volatile("cp.async.cg.shared.global [%0], [%1], 16;" :: "r"(dst), "l"(src));
}
__device__ __forceinline__ void cpa_commit() {
    asm volatile("cp.async.commit_group;" ::: "memory");
}
template <int N>
__device__ __forceinline__ void cpa_wait() {
    asm volatile("cp.async.wait_group %0;" :: "n"(N) : "memory");
}

// Fast exp on the FMA pipe. Degree-5 poly for 2^f, rel err ~8e-5.
__device__ __forceinline__ float fexp(float x) {
    float y = x * 1.4426950408889634f;
    y = fmaxf(y, -126.0f);
    float fi = floorf(y);
    float f = y - fi;
    float p = 0.0013333558f;
    p = fmaf(p, f, 0.0096181291f);
    p = fmaf(p, f, 0.0555041087f);
    p = fmaf(p, f, 0.2402264923f);
    p = fmaf(p, f, 0.6931471806f);
    p = fmaf(p, f, 1.0f);
    int e = (int)fi;
    return p * __int_as_float((e + 127) << 23);
}

// unpack 8 bf16 (one uint4) to floats
__device__ __forceinline__ void unp8(const uint4& u, float* f) {
    const __nv_bfloat162* h = (const __nv_bfloat162*)&u;
    #pragma unroll
    for (int i = 0; i < 4; i++) {
        float2 t = __bfloat1622float2(h[i]);
        f[2 * i] = t.x; f[2 * i + 1] = t.y;
    }
}

// --------------------- LayerNorm 1 (C-major in, coalesced) -----------------
__global__ __launch_bounds__(256) void ln1_kernel(
    const float* __restrict__ in, const float* __restrict__ gam,
    const float* __restrict__ bet, float* __restrict__ outT)
{
    __shared__ float S[256][33];
    __shared__ float p1[8][32], p2[8][32];
    __shared__ float muS[32], riS[32];
    const int blk = blockIdx.x;          // 256 blocks
    const int b   = blk >> 7;
    const int hw0 = (blk & 127) * 32;
    const int t   = threadIdx.x;
    const int lane = t & 31, wrp = t >> 5;

    const float* ip = in + (size_t)b * CDIM * HWPIX + hw0 + lane;
    #pragma unroll
    for (int it = 0; it < 32; it++) {
        int c = wrp + it * 8;
        S[c][lane] = ip[(size_t)c * HWPIX];
    }
    __syncthreads();

    {
        int cb = wrp * 32;
        float s1 = 0.f, s2 = 0.f;
        #pragma unroll
        for (int i = 0; i < 32; i++) {
            float v = S[cb + i][lane];
            s1 += v;
            s2 = fmaf(v, v, s2);
        }
        p1[wrp][lane] = s1;
        p2[wrp][lane] = s2;
    }
    __syncthreads();
    if (t < 32) {
        float s1 = 0.f, s2 = 0.f;
        #pragma unroll
        for (int i = 0; i < 8; i++) { s1 += p1[i][t]; s2 += p2[i][t]; }
        float mu = s1 * (1.0f / 256.0f);
        float var = s2 * (1.0f / 256.0f) - mu * mu;
        muS[t] = mu;
        riS[t] = rsqrtf(var + 1e-5f);
    }
    __syncthreads();

    #pragma unroll
    for (int it = 0; it < 32; it++) {
        int p = wrp * 4 + (it & 3);
        int c = lane + (it >> 2) * 32;
        float v = (S[c][p] - muS[p]) * riS[p] * gam[c] + bet[c];
        outT[((size_t)b * HWPIX + hw0 + p) * 256 + c] = v;
    }
}

// ----------------------------- LayerNorm (generic strides) -----------------
__global__ __launch_bounds__(256) void ln_kernel(
    const float* __restrict__ in, const float* __restrict__ gam,
    const float* __restrict__ bet, float* __restrict__ outT,
    size_t bStride, size_t cStride, size_t pStride)
{
    int p  = blockIdx.x;            // 0..8191
    int b  = p >> 12;
    int hw = p & 4095;
    const float* ip = in + (size_t)b * bStride + (size_t)hw * pStride;
    int c = threadIdx.x;
    float v = ip[(size_t)c * cStride];
    float s1 = v, s2 = v * v;
    #pragma unroll
    for (int d = 16; d > 0; d >>= 1) {
        s1 += __shfl_xor_sync(0xffffffffu, s1, d);
        s2 += __shfl_xor_sync(0xffffffffu, s2, d);
    }
    __shared__ float sm1[8], sm2[8];
    __shared__ float mu_s, ri_s;
    int wid = c >> 5;
    if ((c & 31) == 0) { sm1[wid] = s1; sm2[wid] = s2; }
    __syncthreads();
    if (c == 0) {
        float t1 = 0.f, t2 = 0.f;
        #pragma unroll
        for (int i = 0; i < 8; i++) { t1 += sm1[i]; t2 += sm2[i]; }
        float mu  = t1 * (1.0f / 256.0f);
        float var = t2 * (1.0f / 256.0f) - mu * mu;
        mu_s = mu;
        ri_s = rsqrtf(var + 1e-5f);
    }
    __syncthreads();
    outT[(size_t)p * 256 + c] = (v - mu_s) * ri_s * gam[c] + bet[c];
}

// --------------- GEMM (TN, TF32 tensor core, cp.async double-buffered) ------
// C[z] = A(MxK, lda) * B[z](NxK, ldb)^T (+bias)(gelu?)(+res?).
// Raw f32 staged via cp.async (HW truncates to tf32 in the MMA — implicit
// tf32 path); tile k+1 staged while tile k computes.
#define GF_OUT_NMAJOR 1
#define GF_RES_NMAJOR 2
#define GF_GELU       4
#define GF_GROUPED    8
#define GF_OUT_BF16   16

__global__ __launch_bounds__(256) void gemm_tn(
    const float* __restrict__ A, int lda,
    const float* __restrict__ Bm, int ldb, size_t bZ,
    const float* __restrict__ bias, const float* __restrict__ res,
    float* __restrict__ C, int M, int N, int K, int flags)
{
    __shared__ float As[2][128][36];
    __shared__ float Bs[2][64][36];
    const int b  = blockIdx.z;
    const int m0 = blockIdx.y * 128;
    const int n0 = blockIdx.x * 64;
    const float* Ab = A;
    const float* Bb;
    if (flags & GF_GROUPED) {
        Ab = A + (b & 1) * 128;
        Bb = Bm + (size_t)(b >> 1) * ((size_t)HWPIX * 256) + (b & 1) * 128;
    } else {
        Bb = Bm + (size_t)b * bZ;
    }
    const int tid  = threadIdx.x;
    const int warp = tid >> 5, lane = tid & 31;
    const int g = lane >> 2, tg = lane & 3;
    const int wm = warp & 3;
    const int wn = warp >> 2;

    // staging maps (16B chunks): A: 1024 chunks (4/thread), B: 512 (2/thread)
    const int aRow = tid >> 1, aCh = (tid & 1) << 2;          // +0,+64 rows; ch 0..7 via i
    const int bRow = tid >> 2, bCh = (tid & 3) << 2;          // rows 0..63

    auto stage = [&](int buf, int k0) {
        #pragma unroll
        for (int i = 0; i < 2; i++) {
            int row = aRow + i * 64;   // 0..127
            #pragma unroll
            for (int j = 0; j < 2; j++) {
                int c4 = aCh + j * 8 + 0;  // chunks at float offsets {aCh, aCh+8} *? 
                // chunk index: (tid&1)*4 + j*... need 8 chunks/row over 2 lanes:
                // lane half 0 -> chunks 0..3? Simplify: 4 chunks per (row,thread-half)
                (void)c4;
            }
        }
    };
    (void)stage;

    // Simpler explicit staging: A has 128*8=1024 16B chunks; thread t does
    // chunks t, t+256, t+512, t+768. B has 512 chunks; thread t does t, t+256.
    auto stageA = [&](int buf, int k0) {
        #pragma unroll
        for (int i = 0; i < 4; i++) {
            int e = tid + i * 256;
            int row = e >> 3, c4 = (e & 7) << 2;
            cpa16(smem_u32(&As[buf][row][c4]),
                  Ab + (size_t)(m0 + row) * lda + k0 + c4);
        }
    };
    auto stageB = [&](int buf, int k0) {
        #pragma unroll
        for (int i = 0; i < 2; i++) {
            int e = tid + i * 256;
            int row = e >> 3, c4 = (e & 7) << 2;
            cpa16(smem_u32(&Bs[buf][row][c4]),
                  Bb + (size_t)(n0 + row) * ldb + k0 + c4);
        }
    };

    float acc[2][4][4];
    #pragma unroll
    for (int mi = 0; mi < 2; mi++)
        #pragma unroll
        for (int nj = 0; nj < 4; nj++)
            #pragma unroll
            for (int e = 0; e < 4; e++) acc[mi][nj][e] = 0.f;

    const int nk = K >> 5;
    stageA(0, 0);
    stageB(0, 0);
    cpa_commit();

    for (int ki = 0; ki < nk; ki++) {
        int cur = ki & 1;
        if (ki + 1 < nk) {
            stageA(cur ^ 1, (ki + 1) << 5);
            stageB(cur ^ 1, (ki + 1) << 5);
            cpa_commit();
            cpa_wait<1>();
        } else {
            cpa_wait<0>();
        }
        __syncthreads();

        #pragma unroll
        for (int kk = 0; kk < 4; kk++) {
            int kb = kk * 8;
            uint32_t af[2][4], bf[4][2];
            #pragma unroll
            for (int mi = 0; mi < 2; mi++) {
                int mr = wm * 32 + mi * 16;
                af[mi][0] = __float_as_uint(As[cur][mr + g    ][kb + tg    ]);
                af[mi][1] = __float_as_uint(As[cur][mr + g + 8][kb + tg    ]);
                af[mi][2] = __float_as_uint(As[cur][mr + g    ][kb + tg + 4]);
                af[mi][3] = __float_as_uint(As[cur][mr + g + 8][kb + tg + 4]);
            }
            #pragma unroll
            for (int nj = 0; nj < 4; nj++) {
                int nr = wn * 32 + nj * 8;
                bf[nj][0] = __float_as_uint(Bs[cur][nr + g][kb + tg    ]);
                bf[nj][1] = __float_as_uint(Bs[cur][nr + g][kb + tg + 4]);
            }
            #pragma unroll
            for (int mi = 0; mi < 2; mi++)
                #pragma unroll
                for (int nj = 0; nj < 4; nj++)
                    mma_tf32(acc[mi][nj], af[mi], bf[nj]);
        }
        __syncthreads();
    }

    #pragma unroll
    for (int mi = 0; mi < 2; mi++) {
        #pragma unroll
        for (int nj = 0; nj < 4; nj++) {
            int nc = n0 + wn * 32 + nj * 8 + tg * 2;
            #pragma unroll
            for (int e = 0; e < 4; e++) {
                int m = m0 + wm * 32 + mi * 16 + g + (e >> 1) * 8;
                int n = nc + (e & 1);
                float v = acc[mi][nj][e];
                if (bias) v += bias[m];
                if (flags & GF_GELU) v = geluf(v);
                if (res) {
                    size_t ri = (flags & GF_RES_NMAJOR)
                        ? ((size_t)b * N + n) * (size_t)M + m
                        : ((size_t)b * M + m) * (size_t)N + n;
                    v += res[ri];
                }
                size_t oi = (flags & GF_OUT_NMAJOR)
                    ? ((size_t)b * N + n) * (size_t)M + m
                    : ((size_t)b * M + m) * (size_t)N + n;
                if (flags & GF_OUT_BF16)
                    ((__nv_bfloat16*)C)[oi] = __float2bfloat16(v);
                else
                    C[oi] = v;
            }
        }
    }
}

// ---------------- fused offset path: 3x dw conv + BN + GELU + transpose -----
__global__ __launch_bounds__(256) void dw_fused(
    const float* __restrict__ qin, const float* __restrict__ w1g,
    const float* __restrict__ w2g, const float* __restrict__ w3g,
    const float* __restrict__ bng, const float* __restrict__ bnb,
    const float* __restrict__ bnm, const float* __restrict__ bnv,
    float* __restrict__ oT)
{
    __shared__ float S1[64][65];
    __shared__ float S2[32][33];
    __shared__ float S3[16][17];
    const int blk = blockIdx.x;       // 512
    const int gI = blk >> 7, c = blk & 127;
    const int tid = threadIdx.x;
    const float* ip = qin + (size_t)(gI * 128 + c) * 4096;

    for (int e = tid; e < 4096; e += 256)
        S1[e >> 6][e & 63] = ip[e];

    float w1[9], w2[9], w3[9];
    #pragma unroll
    for (int i = 0; i < 9; i++) {
        w1[i] = w1g[c * 9 + i];
        w2[i] = w2g[c * 9 + i];
        w3[i] = w3g[c * 9 + i];
    }
    __syncthreads();

    #pragma unroll
    for (int i = 0; i < 4; i++) {
        int o = tid * 4 + i;
        int oy = o >> 5, ox = o & 31;
        float s = 0.f;
        #pragma unroll
        for (int ky = 0; ky < 3; ky++) {
            int iy = oy * 2 - 1 + ky;
            if (iy < 0 || iy >= 64) continue;
            #pragma unroll
            for (int kx = 0; kx < 3; kx++) {
                int ix = ox * 2 - 1 + kx;
                if (ix < 0 || ix >= 64) continue;
                s = fmaf(S1[iy][ix], w1[ky * 3 + kx], s);
            }
        }
        S2[oy][ox] = s;
    }
    __syncthreads();

    {
        int oy = tid >> 4, ox = tid & 15;
        float s = 0.f;
        #pragma unroll
        for (int ky = 0; ky < 3; ky++) {
            int iy = oy * 2 - 1 + ky;
            if (iy < 0 || iy >= 32) continue;
            #pragma unroll
            for (int kx = 0; kx < 3; kx++) {
                int ix = ox * 2 - 1 + kx;
                if (ix < 0 || ix >= 32) continue;
                s = fmaf(S2[iy][ix], w2[ky * 3 + kx], s);
            }
        }
        S3[oy][ox] = s;
    }
    __syncthreads();

    if (tid < 64) {
        int oy = tid >> 3, ox = tid & 7;
        float s = 0.f;
        #pragma unroll
        for (int ky = 0; ky < 3; ky++) {
            int iy = oy * 2 - 1 + ky;
            if (iy < 0 || iy >= 16) continue;
            #pragma unroll
            for (int kx = 0; kx < 3; kx++) {
                int ix = ox * 2 - 1 + kx;
                if (ix < 0 || ix >= 16) continue;
                s = fmaf(S3[iy][ix], w3[ky * 3 + kx], s);
            }
        }
        s = (s - bnm[c]) * rsqrtf(bnv[c] + 1e-5f) * bng[c] + bnb[c];
        s = geluf(s);
        oT[(size_t)(gI * 64 + oy * 8 + ox) * 128 + c] = s;
    }
}

// ------------- attention with FUSED deformable k/v sampling (R14) -----------
__global__ __launch_bounds__(128) void attn_kernel(
    const float* __restrict__ qb, const float* __restrict__ offr,
    const __nv_bfloat16* __restrict__ pkT, const __nv_bfloat16* __restrict__ pvT,
    const float* __restrict__ kb, const float* __restrict__ vb,
    const float* __restrict__ pos, float* __restrict__ outT)
{
    __shared__ float Qs[64][36];
    __shared__ float Ks[64][36];
    __shared__ float VsT[32][69];
    __shared__ float Ps[64][68];
    __shared__ float4 s_gw[64][2];
    __shared__ int    s_gp[64][2][4];
    __shared__ float  s_kb[32], s_vb[32];

    const int w = blockIdx.x, h = blockIdx.y, b = blockIdx.z;
    const int wh = w >> 3, wwx = w & 7;
    const int tid = threadIdx.x;
    const int warp = tid >> 5, lane = tid & 31;
    const int g = lane >> 2, tg = lane & 3;

    if (tid < 32)       s_kb[tid] = kb[h * 32 + tid];
    else if (tid < 64)  s_vb[tid - 32] = vb[h * 32 + tid - 32];

    for (int e = tid; e < 2048; e += 128) {
        int qq = e >> 5, c = e & 31;
        int yy = (wh << 3) + (qq >> 3), xx = (wwx << 3) + (qq & 7);
        Qs[qq][c] = to_tf32(qb[(size_t)(b * 256 + h * 32 + c) * HWPIX + yy * 64 + xx] * 0.0625f);
    }

    const int qA = warp * 16 + g, qB = qA + 8;
    const int yA = (wh << 3) + (qA >> 3), xA = (wwx << 3) + (qA & 7);
    const int yB = (wh << 3) + (qB >> 3), xB = (wwx << 3) + (qB & 7);
    const float* poshA = pos + h * 127 * 127 + (63 - yA) * 127 + (63 - xA);
    const float* poshB = pos + h * 127 * 127 + (63 - yB) * 127 + (63 - xB);

    float mA = -1e30f, sA = 0.f, mB = -1e30f, sB = 0.f;
    float O[4][4];
    #pragma unroll
    for (int nj = 0; nj < 4; nj++)
        #pragma unroll
        for (int e = 0; e < 4; e++) O[nj][e] = 0.f;

    const int srow = tid >> 1, shalf = tid & 1;
    const int chof = h * 32 + shalf * 16;

    for (int r0 = 0; r0 < 1024; r0 += 64) {
        __syncthreads();
        {
            int rr = r0 + (tid >> 1);
            int hg = tid & 1;
            int gg = b * 2 + hg;
            float offRow = offr[(size_t)(gg * 2048 + rr) * 64 + w];
            float offCol = offr[(size_t)(gg * 2048 + 1024 + rr) * 64 + w];
            float rows = fmaf(tanhf(offRow), 0.984375f, (float)((rr >> 5) << 1));
            float cols = fmaf(tanhf(offCol), 0.984375f, (float)((rr & 31) << 1));
            float r0f = floorf(rows), c0f = floorf(cols);
            float fr = rows - r0f, fc = cols - c0f;
            int ri = (int)r0f, ci = (int)c0f;
            bool rv0 = (ri >= 0) && (ri < 64);
            bool rv1 = (ri + 1 >= 0) && (ri + 1 < 64);
            bool cv0 = (ci >= 0) && (ci < 64);
            bool cv1 = (ci + 1 >= 0) && (ci + 1 < 64);
            s_gp[tid >> 1][hg][0] = (rv0 && cv0) ? ri * 64 + ci : -1;
            s_gp[tid >> 1][hg][1] = (rv0 && cv1) ? ri * 64 + ci + 1 : -1;
            s_gp[tid >> 1][hg][2] = (rv1 && cv0) ? (ri + 1) * 64 + ci : -1;
            s_gp[tid >> 1][hg][3] = (rv1 && cv1) ? (ri + 1) * 64 + ci + 1 : -1;
            s_gw[tid >> 1][hg] = make_float4((1.f - fr) * (1.f - fc), (1.f - fr) * fc,
                                             fr * (1.f - fc),         fr * fc);
        }
        __syncthreads();

        {
            float ak[16], av[16];
            #pragma unroll
            for (int j = 0; j < 16; j++) {
                ak[j] = s_kb[shalf * 16 + j];
                av[j] = s_vb[shalf * 16 + j];
            }
            #pragma unroll
            for (int hg = 0; hg < 2; hg++) {
                const float4 ww = s_gw[srow][hg];
                const float wts[4] = {ww.x, ww.y, ww.z, ww.w};
                const __nv_bfloat16* pk0 =
                    pkT + (size_t)(b * 2 + hg) * HWPIX * 256 + chof;
                const __nv_bfloat16* pv0 =
                    pvT + (size_t)(b * 2 + hg) * HWPIX * 256 + chof;
                #pragma unroll
                for (int cn = 0; cn < 4; cn++) {
                    int pix = s_gp[srow][hg][cn];
                    if (pix >= 0) {
                        size_t off = (size_t)pix * 256;
                        uint4 ku0 = *(const uint4*)(pk0 + off);
                        uint4 ku1 = *(const uint4*)(pk0 + off + 8);
                        uint4 vu0 = *(const uint4*)(pv0 + off);
                        uint4 vu1 = *(const uint4*)(pv0 + off + 8);
                        float kf[16], vf[16];
                        unp8(ku0, kf); unp8(ku1, kf + 8);
                        unp8(vu0, vf); unp8(vu1, vf + 8);
                        float wt = wts[cn];
                        #pragma unroll
                        for (int j = 0; j < 16; j++) {
                            ak[j] = fmaf(kf[j], wt, ak[j]);
                            av[j] = fmaf(vf[j], wt, av[j]);
                        }
                    }
                }
            }
            #pragma unroll
            for (int j = 0; j < 16; j++) {
                Ks[srow][shalf * 16 + j] = to_tf32(ak[j]);
                VsT[shalf * 16 + j][srow] = to_tf32(av[j]);
            }
        }
        __syncthreads();

        float S[8][4];
        #pragma unroll
        for (int nj = 0; nj < 8; nj++)
            #pragma unroll
            for (int e = 0; e < 4; e++) S[nj][e] = 0.f;
        #pragma unroll
        for (int kk = 0; kk < 4; kk++) {
            int kbx = kk * 8;
            uint32_t af[4];
            af[0] = __float_as_uint(Qs[warp * 16 + g    ][kbx + tg    ]);
            af[1] = __float_as_uint(Qs[warp * 16 + g + 8][kbx + tg    ]);
            af[2] = __float_as_uint(Qs[warp * 16 + g    ][kbx + tg + 4]);
            af[3] = __float_as_uint(Qs[warp * 16 + g + 8][kbx + tg + 4]);
            #pragma unroll
            for (int nj = 0; nj < 8; nj++) {
                uint32_t bf[2];
                bf[0] = __float_as_uint(Ks[nj * 8 + g][kbx + tg    ]);
                bf[1] = __float_as_uint(Ks[nj * 8 + g][kbx + tg + 4]);
                mma_tf32(S[nj], af, bf);
            }
        }

        #pragma unroll
        for (int nj = 0; nj < 8; nj++) {
            int r0c = r0 + nj * 8 + 2 * tg;
            int r1c = r0c + 1;
            int o0 = ((r0c >> 5) << 1) * 127 + ((r0c & 31) << 1);
            int o1 = ((r1c >> 5) << 1) * 127 + ((r1c & 31) << 1);
            S[nj][0] += poshA[o0];
            S[nj][1] += poshA[o1];
            S[nj][2] += poshB[o0];
            S[nj][3] += poshB[o1];
        }

        float mxA = -1e30f, mxB = -1e30f;
        #pragma unroll
        for (int nj = 0; nj < 8; nj++) {
            mxA = fmaxf(mxA, fmaxf(S[nj][0], S[nj][1]));
            mxB = fmaxf(mxB, fmaxf(S[nj][2], S[nj][3]));
        }
        mxA = fmaxf(mxA, __shfl_xor_sync(0xffffffffu, mxA, 1));
        mxA = fmaxf(mxA, __shfl_xor_sync(0xffffffffu, mxA, 2));
        mxB = fmaxf(mxB, __shfl_xor_sync(0xffffffffu, mxB, 1));
        mxB = fmaxf(mxB, __shfl_xor_sync(0xffffffffu, mxB, 2));
        float mnA = fmaxf(mA, mxA), mnB = fmaxf(mB, mxB);
        float corrA = fexp(mA - mnA), corrB = fexp(mB - mnB);
        mA = mnA; mB = mnB;

        float suA = 0.f, suB = 0.f;
        #pragma unroll
        for (int nj = 0; nj < 8; nj++) {
            float p0 = fexp(S[nj][0] - mnA);
            float p1 = fexp(S[nj][1] - mnA);
            float p2 = fexp(S[nj][2] - mnB);
            float p3 = fexp(S[nj][3] - mnB);
            suA += p0 + p1;
            suB += p2 + p3;
            int c0 = nj * 8 + 2 * tg;
            Ps[warp * 16 + g    ][c0    ] = to_tf32(p0);
            Ps[warp * 16 + g    ][c0 + 1] = to_tf32(p1);
            Ps[warp * 16 + g + 8][c0    ] = to_tf32(p2);
            Ps[warp * 16 + g + 8][c0 + 1] = to_tf32(p3);
        }
        suA += __shfl_xor_sync(0xffffffffu, suA, 1);
        suA += __shfl_xor_sync(0xffffffffu, suA, 2);
        suB += __shfl_xor_sync(0xffffffffu, suB, 1);
        suB += __shfl_xor_sync(0xffffffffu, suB, 2);
        sA = sA * corrA + suA;
        sB = sB * corrB + suB;

        #pragma unroll
        for (int nj = 0; nj < 4; nj++) {
            O[nj][0] *= corrA; O[nj][1] *= corrA;
            O[nj][2] *= corrB; O[nj][3] *= corrB;
        }
        __syncwarp();
        __syncthreads();

        #pragma unroll
        for (int kk = 0; kk < 8; kk++) {
            int kbx = kk * 8;
            uint32_t af[4];
            af[0] = __float_as_uint(Ps[warp * 16 + g    ][kbx + tg    ]);
            af[1] = __float_as_uint(Ps[warp * 16 + g + 8][kbx + tg    ]);
            af[2] = __float_as_uint(Ps[warp * 16 + g    ][kbx + tg + 4]);
            af[3] = __float_as_uint(Ps[warp * 16 + g + 8][kbx + tg + 4]);
            #pragma unroll
            for (int nj = 0; nj < 4; nj++) {
                uint32_t bf[2];
                bf[0] = __float_as_uint(VsT[nj * 8 + g][kbx + tg    ]);
                bf[1] = __float_as_uint(VsT[nj * 8 + g][kbx + tg + 4]);
                mma_tf32(O[nj], af, bf);
            }
        }
    }

    float invA = 1.0f / sA, invB = 1.0f / sB;
    float* opA = outT + ((size_t)b * HWPIX + yA * 64 + xA) * 256 + h * 32;
    float* opB = outT + ((size_t)b * HWPIX + yB * 64 + xB) * 256 + h * 32;
    #pragma unroll
    for (int nj = 0; nj < 4; nj++) {
        int c = nj * 8 + 2 * tg;
        opA[c]     = O[nj][0] * invA;
        opA[c + 1] = O[nj][1] * invA;
        opB[c]     = O[nj][2] * invB;
        opB[c + 1] = O[nj][3] * invB;
    }
}

// ------------------------------ launch -------------------------------------
extern "C" void kernel_launch(void* const* d_in, const int* in_sizes, int n_in,
                              void* d_out, int out_size)
{
    const float* x      = (const float*)d_in[0];
    const float* ln1_g  = (const float*)d_in[1];
    const float* ln1_b  = (const float*)d_in[2];
    const float* q_w    = (const float*)d_in[3];
    const float* q_b    = (const float*)d_in[4];
    const float* k_w    = (const float*)d_in[5];
    const float* k_b    = (const float*)d_in[6];
    const float* v_w    = (const float*)d_in[7];
    const float* v_b    = (const float*)d_in[8];
    const float* off1_w = (const float*)d_in[9];
    const float* off2_w = (const float*)d_in[10];
    const float* off3_w = (const float*)d_in[11];
    const float* bn_g   = (const float*)d_in[12];
    const float* bn_b   = (const float*)d_in[13];
    const float* bn_m   = (const float*)d_in[14];
    const float* bn_v   = (const float*)d_in[15];
    const float* off4_w = (const float*)d_in[16];
    const float* pos    = (const float*)d_in[17];
    const float* proj_w = (const float*)d_in[18];
    const float* proj_b = (const float*)d_in[19];
    const float* ln2_g  = (const float*)d_in[20];
    const float* ln2_b  = (const float*)d_in[21];
    const float* mlp_w1 = (const float*)d_in[22];
    const float* mlp_b1 = (const float*)d_in[23];
    const float* mlp_w2 = (const float*)d_in[24];
    const float* mlp_b2 = (const float*)d_in[25];
    float* out = (float*)d_out;

    float *xaT, *q, *oT, *offr, *attnT, *x2, *xmT, *hidT;
    __nv_bfloat16 *pkB, *pvB;
    cudaGetSymbolAddress((void**)&xaT,   g_xaT);
    cudaGetSymbolAddress((void**)&q,     g_q);
    cudaGetSymbolAddress((void**)&oT,    g_oT);
    cudaGetSymbolAddress((void**)&offr,  g_offr);
    cudaGetSymbolAddress((void**)&pkB,   g_pk);
    cudaGetSymbolAddress((void**)&pvB,   g_pv);
    cudaGetSymbolAddress((void**)&attnT, g_attnT);
    cudaGetSymbolAddress((void**)&x2,    g_x2);
    cudaGetSymbolAddress((void**)&xmT,   g_xmT);
    cudaGetSymbolAddress((void**)&hidT,  g_hidT);

    // 1. LN1 (coalesced transpose kernel): x C-major -> xaT pixel-major
    ln1_kernel<<<256, 256>>>(x, ln1_g, ln1_b, xaT);

    // 2. q = q_w @ xa + q_b  -> C-major (B,256,4096)
    gemm_tn<<<dim3(HWPIX / 64, CDIM / 128, NB), 256>>>(
        q_w, CDIM, xaT, CDIM, (size_t)HWPIX * CDIM,
        q_b, nullptr, q, CDIM, HWPIX, CDIM, 0);

    // 3. fused offset path: 3x dw conv + BN + GELU + transpose -> oT
    dw_fused<<<512, 256>>>(q, off1_w, off2_w, off3_w,
                           bn_g, bn_b, bn_m, bn_v, oT);

    // 4. off4 -> offr C-major (4,2048,64)
    gemm_tn<<<dim3(1, 2048 / 128, 4), 256>>>(
        off4_w, 128, oT, 128, (size_t)64 * 128,
        nullptr, nullptr, offr, 2048, 64, 128, 0);

    // 5a/5b. partial conv maps -> bf16 pixel-major (L2-resident, 8MB total)
    gemm_tn<<<dim3(HWPIX / 64, 2, 4), 256>>>(
        k_w, CDIM, xaT, CDIM, 0,
        nullptr, nullptr, (float*)pkB, CDIM, HWPIX, GC,
        GF_GROUPED | GF_OUT_NMAJOR | GF_OUT_BF16);
    gemm_tn<<<dim3(HWPIX / 64, 2, 4), 256>>>(
        v_w, CDIM, xaT, CDIM, 0,
        nullptr, nullptr, (float*)pvB, CDIM, HWPIX, GC,
        GF_GROUPED | GF_OUT_NMAJOR | GF_OUT_BF16);

    // 6. attention with fused deformable sampling -> attnT pixel-major
    attn_kernel<<<dim3(NWIN, HEADS, NB), 128>>>(
        q, offr, pkB, pvB, k_b, v_b, pos, attnT);

    // 7. proj + residual(x, C-major) -> x2 pixel-major
    gemm_tn<<<dim3(HWPIX / 64, CDIM / 128, NB), 256>>>(
        proj_w, CDIM, attnT, CDIM, (size_t)HWPIX * CDIM,
        proj_b, x, x2, CDIM, HWPIX, CDIM, GF_OUT_NMAJOR);

    // 8. LN2 on x2 (pixel-major) -> xmT pixel-major
    ln_kernel<<<8192, 256>>>(x2, ln2_g, ln2_b, xmT,
                             (size_t)HWPIX * CDIM, (size_t)1, (size_t)CDIM);

    // 9. mlp1 + gelu -> hidT pixel-major (B,4096,1024)
    gemm_tn<<<dim3(HWPIX / 64, MLPH / 128, NB), 256>>>(
        mlp_w1, CDIM, xmT, CDIM, (size_t)HWPIX * CDIM,
        mlp_b1, nullptr, hidT, MLPH, HWPIX, CDIM, GF_OUT_NMAJOR | GF_GELU);

    // 10. mlp2 + residual(x2, pixel-major) -> out C-major (B,256,64,64)
    gemm_tn<<<dim3(HWPIX / 64, CDIM / 128, NB), 256>>>(
        mlp_w2, MLPH, hidT, MLPH, (size_t)HWPIX * MLPH,
        mlp_b2, x2, out, CDIM, HWPIX, MLPH, GF_RES_NMAJOR);
}